// round 16
// baseline (speedup 1.0000x reference)
#include <cuda_runtime.h>

#define D_DIM 768
#define H_DIM 64
#define SEQ   4096
#define BATCH 8
#define QSCALE (0.125f * 1.4426950408889634f)   // 1/sqrt(64) * log2(e)

// Scratch (allocation-free rule: __device__ globals), 16B-aligned for cp.async.
// g_q: [b][s][h'] tf32, h' interleaved, pre-scaled by QSCALE
// g_k: [b][s][h'] tf32, h' interleaved
// g_v: [b][h][s]  tf32, TRANSPOSED, natural s order (P-as-A-frag convention)
__device__ __align__(16) float g_q[(size_t)BATCH * SEQ * H_DIM];
__device__ __align__(16) float g_k[(size_t)BATCH * SEQ * H_DIM];
__device__ __align__(16) float g_v[(size_t)BATCH * SEQ * H_DIM];

__device__ __forceinline__ unsigned f2tf(float f) {
    unsigned u;
    asm("cvt.rna.tf32.f32 %0, %1;" : "=r"(u) : "f"(f));
    return u;
}

__device__ __forceinline__ float ex2(float f) {
    float r;
    asm("ex2.approx.ftz.f32 %0, %1;" : "=f"(r) : "f"(f));
    return r;
}

__device__ __forceinline__ void mma_tf32(float c[4], const unsigned a[4],
                                         unsigned b0, unsigned b1) {
    asm volatile(
        "mma.sync.aligned.m16n8k8.row.col.f32.tf32.tf32.f32 "
        "{%0,%1,%2,%3}, {%4,%5,%6,%7}, {%8,%9}, {%0,%1,%2,%3};\n"
        : "+f"(c[0]), "+f"(c[1]), "+f"(c[2]), "+f"(c[3])
        : "r"(a[0]), "r"(a[1]), "r"(a[2]), "r"(a[3]), "r"(b0), "r"(b1));
}

#define CPA(d, s) asm volatile("cp.async.cg.shared.global [%0], [%1], 16;" \
                               :: "r"(d), "l"(s))
#define CPC()  asm volatile("cp.async.commit_group;")
#define CPW0() asm volatile("cp.async.wait_group 0;")

// ---------------------------------------------------------------------------
// TF32 fused QKV projection, double-buffered (unchanged).
// ---------------------------------------------------------------------------
#define AS 40
#define WS 200
#define PROJ_SMEM ((2 * 128 * AS + 2 * 32 * WS) * 4)   // 92160 B

__global__ __launch_bounds__(256, 1)
void proj_tc_kernel(const float* __restrict__ ix,
                    const float* __restrict__ Wq,
                    const float* __restrict__ Wk,
                    const float* __restrict__ Wv)
{
    extern __shared__ unsigned psm[];
    unsigned* Abuf = psm;
    unsigned* Wbuf = psm + 2 * 128 * AS;

    const int t    = threadIdx.x;
    const int lane = t & 31;
    const int w    = t >> 5;
    const int wm   = w >> 1;
    const int wn   = w & 1;
    const int lg   = lane >> 2;
    const int lq   = lane & 3;
    const int row0 = blockIdx.x * 128;

    float c[2][12][4];
    #pragma unroll
    for (int mt = 0; mt < 2; mt++)
        #pragma unroll
        for (int j = 0; j < 12; j++)
            #pragma unroll
            for (int i = 0; i < 4; i++) c[mt][j][i] = 0.f;

    const int alr   = t >> 3;
    const int alk   = (t & 7) * 4;
    const int abase = (alk & ~7) | ((alk & 4) >> 2);

    int wr[6], wc[6], wc4[6];
    const float* wsrc[6];
    #pragma unroll
    for (int m2 = 0; m2 < 6; m2++) {
        int idx  = t + 256 * m2;
        wr[m2]   = idx / 48;
        wc4[m2]  = (idx % 48) * 4;
        wc[m2]   = wc4[m2] & 63;
        wsrc[m2] = (wc4[m2] < 64) ? Wq : (wc4[m2] < 128) ? Wk : Wv;
    }

    float4 par[4], pwr[6];

    #pragma unroll
    for (int u = 0; u < 4; u++)
        par[u] = *(const float4*)(ix + (size_t)(row0 + u * 32 + alr) * D_DIM + alk);
    #pragma unroll
    for (int m2 = 0; m2 < 6; m2++)
        pwr[m2] = *(const float4*)(wsrc[m2] + (size_t)wr[m2] * H_DIM + wc[m2]);
    #pragma unroll
    for (int u = 0; u < 4; u++) {
        unsigned* dst = &Abuf[(u * 32 + alr) * AS + abase];
        dst[0] = f2tf(par[u].x); dst[2] = f2tf(par[u].y);
        dst[4] = f2tf(par[u].z); dst[6] = f2tf(par[u].w);
    }
    #pragma unroll
    for (int m2 = 0; m2 < 6; m2++)
        *(uint4*)&Wbuf[wr[m2] * WS + wc4[m2]] =
            make_uint4(f2tf(pwr[m2].x), f2tf(pwr[m2].y),
                       f2tf(pwr[m2].z), f2tf(pwr[m2].w));
    __syncthreads();

    for (int i = 0; i < 24; i++) {
        unsigned* Ab = Abuf + (i & 1) * 128 * AS;
        unsigned* Wb = Wbuf + (i & 1) * 32 * WS;

        if (i < 23) {
            int kc = (i + 1) * 32;
            #pragma unroll
            for (int u = 0; u < 4; u++)
                par[u] = *(const float4*)(ix + (size_t)(row0 + u * 32 + alr) * D_DIM + kc + alk);
            #pragma unroll
            for (int m2 = 0; m2 < 6; m2++)
                pwr[m2] = *(const float4*)(wsrc[m2] + (size_t)(kc + wr[m2]) * H_DIM + wc[m2]);
        }

        #pragma unroll
        for (int kt = 0; kt < 4; kt++) {
            unsigned a[2][4];
            #pragma unroll
            for (int mt = 0; mt < 2; mt++) {
                int rr = wm * 32 + mt * 16 + lg;
                uint2 p0 = *(const uint2*)&Ab[rr * AS + kt * 8 + 2 * lq];
                uint2 p1 = *(const uint2*)&Ab[(rr + 8) * AS + kt * 8 + 2 * lq];
                a[mt][0] = p0.x; a[mt][2] = p0.y;
                a[mt][1] = p1.x; a[mt][3] = p1.y;
            }
            const unsigned* wb0 = &Wb[(kt * 8 + lq) * WS + wn * 96 + lg];
            const unsigned* wb1 = &Wb[(kt * 8 + 4 + lq) * WS + wn * 96 + lg];
            #pragma unroll
            for (int j = 0; j < 12; j++) {
                unsigned b0 = wb0[j * 8];
                unsigned b1 = wb1[j * 8];
                mma_tf32(c[0][j], a[0], b0, b1);
                mma_tf32(c[1][j], a[1], b0, b1);
            }
        }

        if (i < 23) {
            unsigned* An = Abuf + ((i + 1) & 1) * 128 * AS;
            unsigned* Wn = Wbuf + ((i + 1) & 1) * 32 * WS;
            #pragma unroll
            for (int u = 0; u < 4; u++) {
                unsigned* dst = &An[(u * 32 + alr) * AS + abase];
                dst[0] = f2tf(par[u].x); dst[2] = f2tf(par[u].y);
                dst[4] = f2tf(par[u].z); dst[6] = f2tf(par[u].w);
            }
            #pragma unroll
            for (int m2 = 0; m2 < 6; m2++)
                *(uint4*)&Wn[wr[m2] * WS + wc4[m2]] =
                    make_uint4(f2tf(pwr[m2].x), f2tf(pwr[m2].y),
                               f2tf(pwr[m2].z), f2tf(pwr[m2].w));
        }
        __syncthreads();
    }

    // ---- epilogue: pre-converted scatter (V: transposed, natural s order)
    #pragma unroll
    for (int mt = 0; mt < 2; mt++) {
        int r  = row0 + wm * 32 + mt * 16 + lg;
        int bb = r >> 12;
        int ss = r & (SEQ - 1);
        #pragma unroll
        for (int j = 0; j < 12; j++) {
            int n = wn * 96 + j * 8 + 2 * lq;
            if (n < 64) {
                int p0 = (n & ~7) | ((n & 3) << 1) | ((n & 4) >> 2);
                g_q[(size_t)r * 64 + p0]           = __uint_as_float(f2tf(c[mt][j][0] * QSCALE));
                g_q[(size_t)r * 64 + p0 + 2]       = __uint_as_float(f2tf(c[mt][j][1] * QSCALE));
                g_q[(size_t)(r + 8) * 64 + p0]     = __uint_as_float(f2tf(c[mt][j][2] * QSCALE));
                g_q[(size_t)(r + 8) * 64 + p0 + 2] = __uint_as_float(f2tf(c[mt][j][3] * QSCALE));
            } else if (n < 128) {
                int nc = n - 64;
                int p0 = (nc & ~7) | ((nc & 3) << 1) | ((nc & 4) >> 2);
                g_k[(size_t)r * 64 + p0]           = __uint_as_float(f2tf(c[mt][j][0]));
                g_k[(size_t)r * 64 + p0 + 2]       = __uint_as_float(f2tf(c[mt][j][1]));
                g_k[(size_t)(r + 8) * 64 + p0]     = __uint_as_float(f2tf(c[mt][j][2]));
                g_k[(size_t)(r + 8) * 64 + p0 + 2] = __uint_as_float(f2tf(c[mt][j][3]));
            } else {
                int h = n - 128;
                size_t base = ((size_t)bb * 64 + h) * SEQ;
                g_v[base + ss]           = __uint_as_float(f2tf(c[mt][j][0]));
                g_v[base + SEQ + ss]     = __uint_as_float(f2tf(c[mt][j][1]));
                g_v[base + ss + 8]       = __uint_as_float(f2tf(c[mt][j][2]));
                g_v[base + SEQ + ss + 8] = __uint_as_float(f2tf(c[mt][j][3]));
            }
        }
    }
}

// ---------------------------------------------------------------------------
// TF32 flash attention, software-pipelined: iteration `it` interleaves
// QK(it) with PV(it-1) (P from registers, computed by last iter's exp).
// Dual independent MMA streams hide the exp chain and LDS latency.
// K double-buffered, V triple-buffered, one barrier + one wait per iter.
// ---------------------------------------------------------------------------
#define KST 72
#define VST 40   // 20 ≡ 4 (mod 16): uint2 B-frag loads conflict-free
#define SMEM_ATTN ((2 * 32 * KST + 3 * 64 * VST) * 4)   // 49152 B
#define NIT (SEQ / 32)

__global__ __launch_bounds__(128, 3)
void attn_kernel(float* __restrict__ out)
{
    extern __shared__ unsigned smu[];
    unsigned* Ktb = smu;                  // 2 x [32][KST]
    unsigned* Vtb = Ktb + 2 * 32 * KST;   // 3 x [64][VST] transposed [h][s]

    const int t    = threadIdx.x;
    const int lane = t & 31;
    const int w    = t >> 5;      // 0..3
    const int lg   = lane >> 2;   // 0..7
    const int lq   = lane & 3;    // 0..3
    const int b    = blockIdx.y;
    const int q0   = blockIdx.x * 64;

    const int lr  = t >> 4;          // 0..7   (64-col rows: K)
    const int lc  = (t & 15) * 4;    // 0..60
    const int vlr = t >> 3;          // 0..15  (32-col rows: V)
    const int vlc = (t & 7) * 4;     // 0..28

    const float* kg = g_k + (size_t)b * SEQ * H_DIM;
    const float* vg = g_v + (size_t)b * H_DIM * SEQ;   // transposed [h][s]

    const unsigned ksm = (unsigned)__cvta_generic_to_shared(Ktb);
    const unsigned vsm = (unsigned)__cvta_generic_to_shared(Vtb);

    // ---- prologue: async-stage K(0),V(0) into buffer 0
    #pragma unroll
    for (int u = 0; u < 4; u++) {
        int r = u * 8 + lr;
        CPA(ksm + (r * KST + lc) * 4, kg + (size_t)r * H_DIM + lc);
    }
    #pragma unroll
    for (int u = 0; u < 4; u++) {
        int r = u * 16 + vlr;
        CPA(vsm + (r * VST + vlc) * 4, vg + (size_t)r * SEQ + vlc);
    }
    CPC();

    // Q A-fragments straight from pre-interleaved g_q (overlaps cp.async)
    unsigned qa[8][4];
    {
        const float* qr0 = g_q + ((size_t)b * SEQ + q0 + w * 16 + lg) * H_DIM;
        const float* qr1 = qr0 + 8 * H_DIM;
        #pragma unroll
        for (int kt = 0; kt < 8; kt++) {
            uint2 p0 = *(const uint2*)(qr0 + kt * 8 + 2 * lq);
            uint2 p1 = *(const uint2*)(qr1 + kt * 8 + 2 * lq);
            qa[kt][0] = p0.x; qa[kt][1] = p1.x;
            qa[kt][2] = p0.y; qa[kt][3] = p1.y;
        }
    }

    float o[8][4];
    #pragma unroll
    for (int j = 0; j < 8; j++)
        #pragma unroll
        for (int i = 0; i < 4; i++) o[j][i] = 0.f;
    float ll0 = 0.f, ll1 = 0.f;
    unsigned pp[4][4];   // P(it-1) as PV A-fragments (already permuted)

    // ---- peeled iteration 0: QK(0) + exp(0) only
    {
        CPW0();
        __syncthreads();

        // prefetch K(1) -> kbuf 1, V(1) -> vbuf 1
        {
            const float* kp = kg + (size_t)32 * H_DIM;
            const float* vp = vg + 32;
            #pragma unroll
            for (int u = 0; u < 4; u++) {
                int r = u * 8 + lr;
                CPA(ksm + (32 * KST + r * KST + lc) * 4,
                    kp + (size_t)r * H_DIM + lc);
            }
            #pragma unroll
            for (int u = 0; u < 4; u++) {
                int r = u * 16 + vlr;
                CPA(vsm + (64 * VST + r * VST + vlc) * 4,
                    vp + (size_t)r * SEQ + vlc);
            }
            CPC();
        }

        const unsigned* Kt = Ktb;
        float s[4][4];
        #pragma unroll
        for (int j = 0; j < 4; j++)
            #pragma unroll
            for (int i = 0; i < 4; i++) s[j][i] = 0.f;

        #pragma unroll
        for (int kt = 0; kt < 8; kt++) {
            const unsigned* kr = &Kt[lg * KST + kt * 8 + 2 * lq];
            #pragma unroll
            for (int j = 0; j < 4; j++) {
                uint2 bb = *(const uint2*)&kr[j * 8 * KST];
                mma_tf32(s[j], qa[kt], bb.x, bb.y);
            }
        }

        float rs0 = 0.f, rs1 = 0.f;
        #pragma unroll
        for (int j = 0; j < 4; j++) {
            float e0 = __uint_as_float(f2tf(ex2(s[j][0])));
            float e1 = __uint_as_float(f2tf(ex2(s[j][1])));
            float e2 = __uint_as_float(f2tf(ex2(s[j][2])));
            float e3 = __uint_as_float(f2tf(ex2(s[j][3])));
            rs0 += e0 + e1;
            rs1 += e2 + e3;
            pp[j][0] = __float_as_uint(e0);
            pp[j][1] = __float_as_uint(e2);
            pp[j][2] = __float_as_uint(e1);
            pp[j][3] = __float_as_uint(e3);
        }
        rs0 += __shfl_xor_sync(0xffffffffu, rs0, 1);
        rs0 += __shfl_xor_sync(0xffffffffu, rs0, 2);
        rs1 += __shfl_xor_sync(0xffffffffu, rs1, 1);
        rs1 += __shfl_xor_sync(0xffffffffu, rs1, 2);
        ll0 += rs0;
        ll1 += rs1;
    }

    // ---- main loop: QK(it) fused with PV(it-1)
    for (int it = 1; it < NIT; it++) {
        CPW0();            // K(it), V(it) landed
        __syncthreads();   // everyone done reading K(it-1) & V(it-2)

        if (it < NIT - 1) {
            int kb = (it + 1) & 1;
            int vb3 = (it + 1) % 3;
            const float* kp = kg + (size_t)(it + 1) * 32 * H_DIM;
            const float* vp = vg + (size_t)(it + 1) * 32;
            #pragma unroll
            for (int u = 0; u < 4; u++) {
                int r = u * 8 + lr;
                CPA(ksm + (kb * 32 * KST + r * KST + lc) * 4,
                    kp + (size_t)r * H_DIM + lc);
            }
            #pragma unroll
            for (int u = 0; u < 4; u++) {
                int r = u * 16 + vlr;
                CPA(vsm + (vb3 * 64 * VST + r * VST + vlc) * 4,
                    vp + (size_t)r * SEQ + vlc);
            }
            CPC();
        }

        const unsigned* Kt = Ktb + (it & 1) * 32 * KST;
        const unsigned* Vp = Vtb + ((it - 1) % 3) * 64 * VST;

        float s[4][4];
        #pragma unroll
        for (int j = 0; j < 4; j++)
            #pragma unroll
            for (int i = 0; i < 4; i++) s[j][i] = 0.f;

        // fused dual-stream MMA: QK(it) + PV(it-1)
        #pragma unroll
        for (int kt = 0; kt < 8; kt++) {
            const unsigned* kr = &Kt[lg * KST + kt * 8 + 2 * lq];
            #pragma unroll
            for (int j = 0; j < 4; j++) {
                uint2 bb = *(const uint2*)&kr[j * 8 * KST];
                mma_tf32(s[j], qa[kt], bb.x, bb.y);
            }
            if (kt < 4) {
                const unsigned* vb = &Vp[lg * VST + kt * 8 + 2 * lq];
                #pragma unroll
                for (int j = 0; j < 8; j++) {
                    uint2 vv = *(const uint2*)&vb[j * 8 * VST];
                    mma_tf32(o[j], pp[kt], vv.x, vv.y);
                }
            }
        }

        // exp(it) -> pp (used by next iteration's PV)
        float rs0 = 0.f, rs1 = 0.f;
        #pragma unroll
        for (int j = 0; j < 4; j++) {
            float e0 = __uint_as_float(f2tf(ex2(s[j][0])));
            float e1 = __uint_as_float(f2tf(ex2(s[j][1])));
            float e2 = __uint_as_float(f2tf(ex2(s[j][2])));
            float e3 = __uint_as_float(f2tf(ex2(s[j][3])));
            rs0 += e0 + e1;
            rs1 += e2 + e3;
            pp[j][0] = __float_as_uint(e0);
            pp[j][1] = __float_as_uint(e2);
            pp[j][2] = __float_as_uint(e1);
            pp[j][3] = __float_as_uint(e3);
        }
        rs0 += __shfl_xor_sync(0xffffffffu, rs0, 1);
        rs0 += __shfl_xor_sync(0xffffffffu, rs0, 2);
        rs1 += __shfl_xor_sync(0xffffffffu, rs1, 1);
        rs1 += __shfl_xor_sync(0xffffffffu, rs1, 2);
        ll0 += rs0;
        ll1 += rs1;
    }

    // ---- drain: PV(NIT-1)
    {
        const unsigned* Vp = Vtb + ((NIT - 1) % 3) * 64 * VST;
        #pragma unroll
        for (int kt = 0; kt < 4; kt++) {
            const unsigned* vb = &Vp[lg * VST + kt * 8 + 2 * lq];
            #pragma unroll
            for (int j = 0; j < 8; j++) {
                uint2 vv = *(const uint2*)&vb[j * 8 * VST];
                mma_tf32(o[j], pp[kt], vv.x, vv.y);
            }
        }
    }

    // ---- epilogue
    {
        float inv0 = 1.0f / ll0;
        float inv1 = 1.0f / ll1;
        float* og = out + ((size_t)b * SEQ + q0 + w * 16) * H_DIM;
        #pragma unroll
        for (int j = 0; j < 8; j++) {
            *(float2*)&og[(size_t)lg * H_DIM + j * 8 + 2 * lq] =
                make_float2(o[j][0] * inv0, o[j][1] * inv0);
            *(float2*)&og[(size_t)(lg + 8) * H_DIM + j * 8 + 2 * lq] =
                make_float2(o[j][2] * inv1, o[j][3] * inv1);
        }
    }
}

// ---------------------------------------------------------------------------
extern "C" void kernel_launch(void* const* d_in, const int* in_sizes, int n_in,
                              void* d_out, int out_size)
{
    (void)in_sizes; (void)n_in; (void)out_size;
    // metadata order: ix, Wk, Wq, Wv
    const float* ix = (const float*)d_in[0];
    const float* Wk = (const float*)d_in[1];
    const float* Wq = (const float*)d_in[2];
    const float* Wv = (const float*)d_in[3];
    float* out = (float*)d_out;

    cudaFuncSetAttribute(proj_tc_kernel,
                         cudaFuncAttributeMaxDynamicSharedMemorySize, PROJ_SMEM);
    proj_tc_kernel<<<(BATCH * SEQ) / 128, 256, PROJ_SMEM>>>(ix, Wq, Wk, Wv);

    cudaFuncSetAttribute(attn_kernel,
                         cudaFuncAttributeMaxDynamicSharedMemorySize, SMEM_ATTN);
    attn_kernel<<<dim3(SEQ / 64, BATCH), 128, SMEM_ATTN>>>(out);
}